// round 16
// baseline (speedup 1.0000x reference)
#include <cuda_runtime.h>
#include <cuda_fp16.h>
#include <math.h>
#include <stdint.h>

// Problem constants
#define BATCH   2
#define HW      64
#define SEQ     256
#define DMODEL  512
#define HEADS   8
#define DK      64
#define KSIZE   7
#define NEIGH   3

#define MROWS   (BATCH * HW * SEQ)      // 32768
#define QKV_N   (3 * HEADS * DK)        // 1536
#define NCHUNK  4
#define CHROWS  (MROWS / NCHUNK)        // 8192 rows = 32 sequences per chunk

// GEMM tiling: CTA 128x128, 4 warps @ 64x64 warp tile, fp16 m16n8k16
#define BM 128
#define BN 128
#define BKH 64   // K-tile in halves
#define XSH 80   // smem row stride in halves (160B; word-stride 40 == 8 mod 32)
#define GEMM_THREADS 128

// Scratch (allocation-free: __device__ globals)
__device__ __half g_xt  [(size_t)MROWS * DMODEL];   //  32 MB (fp16, K-perm16)
__device__ float  g_qkv [(size_t)MROWS * QKV_N];    // 201 MB (fp32, natural)
__device__ __half g_att [(size_t)MROWS * DMODEL];   //  32 MB (fp16, K-perm16)
__device__ __half g_wqkvT[(size_t)QKV_N * DMODEL];  // 1.5 MB (Wqkv^T, perm16)
__device__ __half g_woutT[(size_t)DMODEL * DMODEL]; // 0.5 MB (Wout^T, perm16)

// ---------------------------------------------------------------------------
// Helpers
// ---------------------------------------------------------------------------
// 16-chunk K permutation (pairs map to pairs; low bit preserved):
// pos_local(k) = ((k>>1)&3)<<2 | ((k>>3)&1)<<1 | (k&1)
__device__ __host__ __forceinline__ int perm16(int k) {
    return (k & ~15) | (((k >> 1) & 3) << 2) | (((k >> 3) & 1) << 1) | (k & 1);
}

__device__ __forceinline__ uint32_t smem_u32(const void* p) {
    uint32_t a;
    asm("{ .reg .u64 t; cvta.to.shared.u64 t, %1; cvt.u32.u64 %0, t; }"
        : "=r"(a) : "l"(p));
    return a;
}

#define CP_ASYNC16(dst, src) \
    asm volatile("cp.async.cg.shared.global [%0], [%1], 16;" \
                 :: "r"(dst), "l"(src) : "memory")
#define CP_COMMIT() asm volatile("cp.async.commit_group;" ::: "memory")
#define CP_WAIT(n)  asm volatile("cp.async.wait_group %0;" :: "n"(n) : "memory")

__device__ __forceinline__ void mma_f16(float* c, const uint32_t* a,
                                        const uint32_t* b) {
    asm volatile(
        "mma.sync.aligned.m16n8k16.row.col.f32.f16.f16.f32 "
        "{%0,%1,%2,%3}, {%4,%5,%6,%7}, {%8,%9}, {%0,%1,%2,%3};"
        : "+f"(c[0]), "+f"(c[1]), "+f"(c[2]), "+f"(c[3])
        : "r"(a[0]), "r"(a[1]), "r"(a[2]), "r"(a[3]),
          "r"(b[0]), "r"(b[1]));
}

// ---------------------------------------------------------------------------
// fp16 warp-MMA GEMM: C[M,N] = A[M,K] @ Bt[N,K]^T  (perm16 K layout)
// CTA 128x128, 4 warps @ 64x64, BK=64 halves, double-buffered cp.async,
// 2 CTAs/SM, one __syncthreads per K-stage. All fragment loads LDS.64,
// conflict-free (row word-stride 40 == 8 mod 32). R11 pareto config.
// ---------------------------------------------------------------------------
template<int K>
__global__ __launch_bounds__(GEMM_THREADS, 2) void gemm_mma_f16(
    const __half* __restrict__ A, const __half* __restrict__ Bt,
    float* __restrict__ C, int M, int N)
{
    extern __shared__ __half smh[];
    __half* Asf = smh;                       // [2][BM][XSH]
    __half* Bsf = smh + 2 * BM * XSH;        // [2][BN][XSH]
    const uint32_t as_u = smem_u32(Asf);
    const uint32_t bs_u = smem_u32(Bsf);

    const int tid  = threadIdx.x;
    const int wid  = tid >> 5;
    const int lane = tid & 31;
    const int gid  = lane >> 2;    // 0..7
    const int tig  = lane & 3;     // 0..3

    const int wm0 = (wid >> 1) * 64;   // warp m-offset (0 or 64)
    const int wn0 = (wid & 1) * 64;    // warp n-offset (0 or 64)

    const int mbase = blockIdx.y * BM;
    const int nbase = blockIdx.x * BN;
    const __half* Ab = A  + (size_t)mbase * K;
    const __half* Bb = Bt + (size_t)nbase * K;

    const int lrow = tid >> 3;          // 0..15
    const int lk8  = (tid & 7) << 3;    // 0,8,...,56 halves (16B each)

    auto load_stage = [&](int s, int buf) {
        const __half* Asrc = Ab + (size_t)s * BKH;
        const __half* Bsrc = Bb + (size_t)s * BKH;
        #pragma unroll
        for (int j = 0; j < 8; j++) {
            int row = lrow + 16 * j;
            uint32_t d = as_u + (((uint32_t)(buf * BM + row) * XSH + lk8) << 1);
            CP_ASYNC16(d, Asrc + (size_t)row * K + lk8);
        }
        #pragma unroll
        for (int j = 0; j < 8; j++) {
            int row = lrow + 16 * j;
            uint32_t d = bs_u + (((uint32_t)(buf * BN + row) * XSH + lk8) << 1);
            CP_ASYNC16(d, Bsrc + (size_t)row * K + lk8);
        }
    };

    float acc[4][8][4];
    #pragma unroll
    for (int mi = 0; mi < 4; mi++)
        #pragma unroll
        for (int ni = 0; ni < 8; ni++)
            #pragma unroll
            for (int q = 0; q < 4; q++) acc[mi][ni][q] = 0.0f;

    const int NSTAGE = K / BKH;   // 8
    load_stage(0, 0);
    CP_COMMIT();

    #pragma unroll 1
    for (int s = 0; s < NSTAGE; s++) {
        CP_WAIT(0);
        __syncthreads();

        if (s + 1 < NSTAGE) {
            load_stage(s + 1, (s + 1) & 1);
            CP_COMMIT();
        }

        const __half* Ab_s = Asf + (s & 1) * BM * XSH;
        const __half* Bb_s = Bsf + (s & 1) * BN * XSH;
        #pragma unroll
        for (int kk = 0; kk < 4; kk++) {
            const int k16 = kk * 16 + 4 * tig;
            uint32_t afr[4][4], bfr[8][2];
            #pragma unroll
            for (int mi = 0; mi < 4; mi++) {
                const __half* r0 = Ab_s + (wm0 + mi * 16 + gid) * XSH + k16;
                uint2 u0 = *(const uint2*)r0;
                uint2 u8 = *(const uint2*)(r0 + 8 * XSH);
                afr[mi][0] = u0.x;
                afr[mi][1] = u8.x;
                afr[mi][2] = u0.y;
                afr[mi][3] = u8.y;
            }
            #pragma unroll
            for (int ni = 0; ni < 8; ni++) {
                const __half* rn = Bb_s + (wn0 + ni * 8 + gid) * XSH + k16;
                uint2 u = *(const uint2*)rn;
                bfr[ni][0] = u.x;
                bfr[ni][1] = u.y;
            }
            #pragma unroll
            for (int mi = 0; mi < 4; mi++)
                #pragma unroll
                for (int ni = 0; ni < 8; ni++)
                    mma_f16(acc[mi][ni], afr[mi], bfr[ni]);
        }
    }

    // Epilogue
    #pragma unroll
    for (int mi = 0; mi < 4; mi++) {
        #pragma unroll
        for (int ni = 0; ni < 8; ni++) {
            const int row = mbase + wm0 + mi * 16 + gid;
            const int col = nbase + wn0 + ni * 8 + tig * 2;
            float2 v0 = make_float2(acc[mi][ni][0], acc[mi][ni][1]);
            float2 v1 = make_float2(acc[mi][ni][2], acc[mi][ni][3]);
            *(float2*)(C + (size_t)row * N + col)       = v0;
            *(float2*)(C + (size_t)(row + 8) * N + col) = v1;
        }
    }
}

// ---------------------------------------------------------------------------
// fp32 -> fp16 convert + perm16, one 16-chunk per thread.
// ---------------------------------------------------------------------------
__global__ void conv_perm_kernel(const float4* __restrict__ in,
                                 __half* __restrict__ out, int n16)
{
    int i = blockIdx.x * blockDim.x + threadIdx.x;
    if (i < n16) {
        float4 f0 = in[4 * i + 0];
        float4 f1 = in[4 * i + 1];
        float4 f2 = in[4 * i + 2];
        float4 f3 = in[4 * i + 3];
        float v[16] = {f0.x, f0.y, f0.z, f0.w, f1.x, f1.y, f1.z, f1.w,
                       f2.x, f2.y, f2.z, f2.w, f3.x, f3.y, f3.z, f3.w};
        __half h[16];
        #pragma unroll
        for (int k = 0; k < 16; k++) {
            const int pos = (((k >> 1) & 3) << 2) | (((k >> 3) & 1) << 1) | (k & 1);
            h[pos] = __float2half_rn(v[k]);
        }
        uint4* dst = (uint4*)(out + 16 * (size_t)i);
        dst[0] = *(uint4*)(h);
        dst[1] = *(uint4*)(h + 8);
    }
}

// ---------------------------------------------------------------------------
// Transpose + fp16 + perm16: out[c][perm16(r)] = half(in[r][c])
// ---------------------------------------------------------------------------
__global__ void transpose_kernel(const float* __restrict__ in,
                                 __half* __restrict__ out, int R, int C)
{
    __shared__ float tile[32][33];
    int x = blockIdx.x * 32 + threadIdx.x;
    int y = blockIdx.y * 32 + threadIdx.y;
    #pragma unroll
    for (int j = 0; j < 32; j += 8)
        tile[threadIdx.y + j][threadIdx.x] = in[(size_t)(y + j) * C + x];
    __syncthreads();
    x = blockIdx.y * 32 + threadIdx.x;   // indexes R (the K dim) -> permute
    y = blockIdx.x * 32 + threadIdx.y;
    const int xp = perm16(x);
    #pragma unroll
    for (int j = 0; j < 32; j += 8)
        out[(size_t)(y + j) * R + xp] =
            __float2half_rn(tile[threadIdx.x][threadIdx.y + j]);
}

// ---------------------------------------------------------------------------
// Local attention: one warp per (row, head); block = 8 consecutive s x one
// head (locality remap). qkv fp32 in; att fp16 (perm16) out.
// Lane owns dims {2*lane, 2*lane+1} -> one float2 load per row access, one
// half2 store (perm16 keeps pairs adjacent).
// ---------------------------------------------------------------------------
__global__ __launch_bounds__(256) void local_attn_kernel(
    const float* __restrict__ qkv, const float* __restrict__ bias,
    __half* __restrict__ out)
{
    const int w    = threadIdx.x >> 5;
    const int lane = threadIdx.x & 31;
    const int sblk = blockIdx.x & (SEQ / 8 - 1);
    const int h    = (blockIdx.x >> 5) & (HEADS - 1);
    const int bhw  = blockIdx.x >> 8;
    const int s = sblk * 8 + w;
    const int r = bhw * SEQ + s;

    const float2* qrow = (const float2*)(qkv + (size_t)r * QKV_N + h * DK);
    const float2 q = qrow[lane];

    float logit[KSIZE];
    #pragma unroll
    for (int ww = 0; ww < KSIZE; ww++) {
        const int sn = s + ww - NEIGH;
        float dot = 0.0f;
        if (sn >= 0 && sn < SEQ) {
            const float2* krow = (const float2*)(
                qkv + (size_t)(r + ww - NEIGH) * QKV_N + HEADS * DK + h * DK);
            float2 kv = krow[lane];
            float t = q.x * kv.x + q.y * kv.y;
            #pragma unroll
            for (int off = 16; off > 0; off >>= 1)
                t += __shfl_xor_sync(0xFFFFFFFFu, t, off);
            dot = t;
        }
        logit[ww] = dot * 0.125f + bias[((size_t)h * SEQ + s) * KSIZE + ww];
    }

    float m = logit[0];
    #pragma unroll
    for (int ww = 1; ww < KSIZE; ww++) m = fmaxf(m, logit[ww]);
    float p[KSIZE];
    float denom = 0.0f;
    #pragma unroll
    for (int ww = 0; ww < KSIZE; ww++) {
        p[ww] = __expf(logit[ww] - m);
        denom += p[ww];
    }
    const float inv = 1.0f / denom;

    float ox = 0.0f, oy = 0.0f;
    #pragma unroll
    for (int ww = 0; ww < KSIZE; ww++) {
        const int sn = s + ww - NEIGH;
        if (sn >= 0 && sn < SEQ) {
            const float2* vrow = (const float2*)(
                qkv + (size_t)(r + ww - NEIGH) * QKV_N + 2 * HEADS * DK + h * DK);
            float2 vv = vrow[lane];
            ox += p[ww] * vv.x;
            oy += p[ww] * vv.y;
        }
    }
    // perm16 maps pair (2j,2j+1) to an aligned pair -> single half2 store
    const int pos = perm16(h * DK + 2 * lane);
    ((__half2*)(out + (size_t)r * DMODEL))[pos >> 1] =
        __floats2half2_rn(ox * inv, oy * inv);
}

// ---------------------------------------------------------------------------
// Launch: 4 row-chunks pipelined across 2 streams. Weight transposes run on
// st[1] concurrently with st[0]'s first conv; st[0] waits on evW before its
// first GEMM1 (GEMM2 needs woutT, which is also covered by evW).
// ---------------------------------------------------------------------------
extern "C" void kernel_launch(void* const* d_in, const int* in_sizes, int n_in,
                              void* d_out, int out_size)
{
    const float* x    = (const float*)d_in[0];  // [2,64,256,512]
    const float* bias = (const float*)d_in[1];  // [8,256,7]
    const float* Wqkv = (const float*)d_in[2];  // [512,1536]
    const float* Wout = (const float*)d_in[3];  // [512,512]
    float* out        = (float*)d_out;          // [32768,512]

    __half *xt, *att, *wqkvT, *woutT;
    float *qkv;
    cudaGetSymbolAddress((void**)&xt,    g_xt);
    cudaGetSymbolAddress((void**)&qkv,   g_qkv);
    cudaGetSymbolAddress((void**)&att,   g_att);
    cudaGetSymbolAddress((void**)&wqkvT, g_wqkvT);
    cudaGetSymbolAddress((void**)&woutT, g_woutT);

    const int dyn_smem = 2 * (BM + BN) * XSH * (int)sizeof(__half);  // 81920

    static cudaStream_t st[2] = {nullptr, nullptr};
    static cudaEvent_t evFork = nullptr;
    static cudaEvent_t evW = nullptr;
    static cudaEvent_t evJoin[2] = {nullptr, nullptr};
    static bool init_done = false;
    if (!init_done) {
        cudaFuncSetAttribute(gemm_mma_f16<DMODEL>,
                             cudaFuncAttributeMaxDynamicSharedMemorySize, dyn_smem);
        cudaStreamCreateWithFlags(&st[0], cudaStreamNonBlocking);
        cudaStreamCreateWithFlags(&st[1], cudaStreamNonBlocking);
        cudaEventCreateWithFlags(&evFork,    cudaEventDisableTiming);
        cudaEventCreateWithFlags(&evW,       cudaEventDisableTiming);
        cudaEventCreateWithFlags(&evJoin[0], cudaEventDisableTiming);
        cudaEventCreateWithFlags(&evJoin[1], cudaEventDisableTiming);
        init_done = true;
    }

    // Fork both streams from the capture-origin (default) stream
    cudaEventRecord(evFork, 0);
    cudaStreamWaitEvent(st[0], evFork, 0);
    cudaStreamWaitEvent(st[1], evFork, 0);

    // Weight transposes on st[1]; overlap with st[0]'s first conv
    {
        dim3 blk(32, 8);
        transpose_kernel<<<dim3(QKV_N / 32, DMODEL / 32), blk, 0, st[1]>>>(
            Wqkv, wqkvT, DMODEL, QKV_N);
        transpose_kernel<<<dim3(DMODEL / 32, DMODEL / 32), blk, 0, st[1]>>>(
            Wout, woutT, DMODEL, DMODEL);
        cudaEventRecord(evW, st[1]);
    }

    for (int c = 0; c < NCHUNK; c++) {
        cudaStream_t s = st[c & 1];
        const size_t ro = (size_t)c * CHROWS;
        const float* xc = x   + ro * DMODEL;
        __half* xtc     = xt  + ro * DMODEL;
        float* qkvc     = qkv + ro * QKV_N;
        __half* attc    = att + ro * DMODEL;
        float* outc     = out + ro * DMODEL;

        const int n16 = CHROWS * DMODEL / 16;
        conv_perm_kernel<<<(n16 + 255) / 256, 256, 0, s>>>(
            (const float4*)xc, xtc, n16);

        if (c == 0) cudaStreamWaitEvent(st[0], evW, 0);  // weights ready

        gemm_mma_f16<DMODEL><<<dim3(QKV_N / BN, CHROWS / BM),
                               GEMM_THREADS, dyn_smem, s>>>(
            xtc, wqkvT, qkvc, CHROWS, QKV_N);

        local_attn_kernel<<<CHROWS, 256, 0, s>>>(qkvc, bias, attc);

        gemm_mma_f16<DMODEL><<<dim3(DMODEL / BN, CHROWS / BM),
                               GEMM_THREADS, dyn_smem, s>>>(
            attc, woutT, outc, CHROWS, DMODEL);
    }

    cudaEventRecord(evJoin[0], st[0]);
    cudaEventRecord(evJoin[1], st[1]);
    cudaStreamWaitEvent(0, evJoin[0], 0);
    cudaStreamWaitEvent(0, evJoin[1], 0);
}

// round 17
// speedup vs baseline: 1.0609x; 1.0609x over previous
#include <cuda_runtime.h>
#include <cuda_fp16.h>
#include <math.h>
#include <stdint.h>

// Problem constants
#define BATCH   2
#define HW      64
#define SEQ     256
#define DMODEL  512
#define HEADS   8
#define DK      64
#define KSIZE   7
#define NEIGH   3

#define MROWS   (BATCH * HW * SEQ)      // 32768
#define QKV_N   (3 * HEADS * DK)        // 1536
#define NCHUNK  4
#define CHROWS  (MROWS / NCHUNK)        // 8192 rows

// GEMM tiling: CTA 128x128, 4 warps @ 64x64 warp tile, fp16 m16n8k16
#define BM 128
#define BN 128
#define BKH 64   // K-tile in halves
#define XSH 80   // smem row stride in halves (160B; word-stride 40 == 8 mod 32)
#define GEMM_THREADS 128

// Scratch (allocation-free: __device__ globals)
__device__ __half g_xt  [(size_t)MROWS * DMODEL];   //  32 MB (fp16, K-perm16)
__device__ float  g_qkv [(size_t)MROWS * QKV_N];    // 201 MB (fp32, natural)
__device__ __half g_att [(size_t)MROWS * DMODEL];   //  32 MB (fp16, K-perm16)
__device__ __half g_wqkvT[(size_t)QKV_N * DMODEL];  // 1.5 MB (Wqkv^T, perm16)
__device__ __half g_woutT[(size_t)DMODEL * DMODEL]; // 0.5 MB (Wout^T, perm16)

// ---------------------------------------------------------------------------
// Helpers
// ---------------------------------------------------------------------------
// 16-chunk K permutation (pairs map to pairs; low bit preserved):
// pos_local(k) = ((k>>1)&3)<<2 | ((k>>3)&1)<<1 | (k&1)
__device__ __host__ __forceinline__ int perm16(int k) {
    return (k & ~15) | (((k >> 1) & 3) << 2) | (((k >> 3) & 1) << 1) | (k & 1);
}

__device__ __forceinline__ uint32_t smem_u32(const void* p) {
    uint32_t a;
    asm("{ .reg .u64 t; cvta.to.shared.u64 t, %1; cvt.u32.u64 %0, t; }"
        : "=r"(a) : "l"(p));
    return a;
}

#define CP_ASYNC16(dst, src) \
    asm volatile("cp.async.cg.shared.global [%0], [%1], 16;" \
                 :: "r"(dst), "l"(src) : "memory")
#define CP_COMMIT() asm volatile("cp.async.commit_group;" ::: "memory")
#define CP_WAIT(n)  asm volatile("cp.async.wait_group %0;" :: "n"(n) : "memory")

__device__ __forceinline__ void mma_f16(float* c, const uint32_t* a,
                                        const uint32_t* b) {
    asm volatile(
        "mma.sync.aligned.m16n8k16.row.col.f32.f16.f16.f32 "
        "{%0,%1,%2,%3}, {%4,%5,%6,%7}, {%8,%9}, {%0,%1,%2,%3};"
        : "+f"(c[0]), "+f"(c[1]), "+f"(c[2]), "+f"(c[3])
        : "r"(a[0]), "r"(a[1]), "r"(a[2]), "r"(a[3]),
          "r"(b[0]), "r"(b[1]));
}

// ---------------------------------------------------------------------------
// fp16 warp-MMA GEMM: C[M,N] = A[M,K] @ Bt[N,K]^T  (perm16 K layout)
// CTA 128x128, 4 warps @ 64x64, BK=64 halves, double-buffered cp.async,
// 2 CTAs/SM, one __syncthreads per K-stage. All fragment loads LDS.64,
// conflict-free (row word-stride 40 == 8 mod 32).
// ---------------------------------------------------------------------------
template<int K>
__global__ __launch_bounds__(GEMM_THREADS, 2) void gemm_mma_f16(
    const __half* __restrict__ A, const __half* __restrict__ Bt,
    float* __restrict__ C, int M, int N)
{
    extern __shared__ __half smh[];
    __half* Asf = smh;                       // [2][BM][XSH]
    __half* Bsf = smh + 2 * BM * XSH;        // [2][BN][XSH]
    const uint32_t as_u = smem_u32(Asf);
    const uint32_t bs_u = smem_u32(Bsf);

    const int tid  = threadIdx.x;
    const int wid  = tid >> 5;
    const int lane = tid & 31;
    const int gid  = lane >> 2;    // 0..7
    const int tig  = lane & 3;     // 0..3

    const int wm0 = (wid >> 1) * 64;   // warp m-offset (0 or 64)
    const int wn0 = (wid & 1) * 64;    // warp n-offset (0 or 64)

    const int mbase = blockIdx.y * BM;
    const int nbase = blockIdx.x * BN;
    const __half* Ab = A  + (size_t)mbase * K;
    const __half* Bb = Bt + (size_t)nbase * K;

    const int lrow = tid >> 3;          // 0..15
    const int lk8  = (tid & 7) << 3;    // 0,8,...,56 halves (16B each)

    auto load_stage = [&](int s, int buf) {
        const __half* Asrc = Ab + (size_t)s * BKH;
        const __half* Bsrc = Bb + (size_t)s * BKH;
        #pragma unroll
        for (int j = 0; j < 8; j++) {
            int row = lrow + 16 * j;
            uint32_t d = as_u + (((uint32_t)(buf * BM + row) * XSH + lk8) << 1);
            CP_ASYNC16(d, Asrc + (size_t)row * K + lk8);
        }
        #pragma unroll
        for (int j = 0; j < 8; j++) {
            int row = lrow + 16 * j;
            uint32_t d = bs_u + (((uint32_t)(buf * BN + row) * XSH + lk8) << 1);
            CP_ASYNC16(d, Bsrc + (size_t)row * K + lk8);
        }
    };

    float acc[4][8][4];
    #pragma unroll
    for (int mi = 0; mi < 4; mi++)
        #pragma unroll
        for (int ni = 0; ni < 8; ni++)
            #pragma unroll
            for (int q = 0; q < 4; q++) acc[mi][ni][q] = 0.0f;

    const int NSTAGE = K / BKH;   // 8
    load_stage(0, 0);
    CP_COMMIT();

    #pragma unroll 1
    for (int s = 0; s < NSTAGE; s++) {
        CP_WAIT(0);
        __syncthreads();

        if (s + 1 < NSTAGE) {
            load_stage(s + 1, (s + 1) & 1);
            CP_COMMIT();
        }

        const __half* Ab_s = Asf + (s & 1) * BM * XSH;
        const __half* Bb_s = Bsf + (s & 1) * BN * XSH;
        #pragma unroll
        for (int kk = 0; kk < 4; kk++) {
            const int k16 = kk * 16 + 4 * tig;
            uint32_t afr[4][4], bfr[8][2];
            #pragma unroll
            for (int mi = 0; mi < 4; mi++) {
                const __half* r0 = Ab_s + (wm0 + mi * 16 + gid) * XSH + k16;
                uint2 u0 = *(const uint2*)r0;
                uint2 u8 = *(const uint2*)(r0 + 8 * XSH);
                afr[mi][0] = u0.x;
                afr[mi][1] = u8.x;
                afr[mi][2] = u0.y;
                afr[mi][3] = u8.y;
            }
            #pragma unroll
            for (int ni = 0; ni < 8; ni++) {
                const __half* rn = Bb_s + (wn0 + ni * 8 + gid) * XSH + k16;
                uint2 u = *(const uint2*)rn;
                bfr[ni][0] = u.x;
                bfr[ni][1] = u.y;
            }
            #pragma unroll
            for (int mi = 0; mi < 4; mi++)
                #pragma unroll
                for (int ni = 0; ni < 8; ni++)
                    mma_f16(acc[mi][ni], afr[mi], bfr[ni]);
        }
    }

    // Epilogue
    #pragma unroll
    for (int mi = 0; mi < 4; mi++) {
        #pragma unroll
        for (int ni = 0; ni < 8; ni++) {
            const int row = mbase + wm0 + mi * 16 + gid;
            const int col = nbase + wn0 + ni * 8 + tig * 2;
            float2 v0 = make_float2(acc[mi][ni][0], acc[mi][ni][1]);
            float2 v1 = make_float2(acc[mi][ni][2], acc[mi][ni][3]);
            *(float2*)(C + (size_t)row * N + col)       = v0;
            *(float2*)(C + (size_t)(row + 8) * N + col) = v1;
        }
    }
}

// ---------------------------------------------------------------------------
// fp32 -> fp16 convert + perm16, one 16-chunk per thread.
// ---------------------------------------------------------------------------
__global__ void conv_perm_kernel(const float4* __restrict__ in,
                                 __half* __restrict__ out, int n16)
{
    int i = blockIdx.x * blockDim.x + threadIdx.x;
    if (i < n16) {
        float4 f0 = in[4 * i + 0];
        float4 f1 = in[4 * i + 1];
        float4 f2 = in[4 * i + 2];
        float4 f3 = in[4 * i + 3];
        float v[16] = {f0.x, f0.y, f0.z, f0.w, f1.x, f1.y, f1.z, f1.w,
                       f2.x, f2.y, f2.z, f2.w, f3.x, f3.y, f3.z, f3.w};
        __half h[16];
        #pragma unroll
        for (int k = 0; k < 16; k++) {
            const int pos = (((k >> 1) & 3) << 2) | (((k >> 3) & 1) << 1) | (k & 1);
            h[pos] = __float2half_rn(v[k]);
        }
        uint4* dst = (uint4*)(out + 16 * (size_t)i);
        dst[0] = *(uint4*)(h);
        dst[1] = *(uint4*)(h + 8);
    }
}

// ---------------------------------------------------------------------------
// Transpose + fp16 + perm16: out[c][perm16(r)] = half(in[r][c])
// ---------------------------------------------------------------------------
__global__ void transpose_kernel(const float* __restrict__ in,
                                 __half* __restrict__ out, int R, int C)
{
    __shared__ float tile[32][33];
    int x = blockIdx.x * 32 + threadIdx.x;
    int y = blockIdx.y * 32 + threadIdx.y;
    #pragma unroll
    for (int j = 0; j < 32; j += 8)
        tile[threadIdx.y + j][threadIdx.x] = in[(size_t)(y + j) * C + x];
    __syncthreads();
    x = blockIdx.y * 32 + threadIdx.x;   // indexes R (the K dim) -> permute
    y = blockIdx.x * 32 + threadIdx.y;
    const int xp = perm16(x);
    #pragma unroll
    for (int j = 0; j < 32; j += 8)
        out[(size_t)(y + j) * R + xp] =
            __float2half_rn(tile[threadIdx.x][threadIdx.y + j]);
}

// ---------------------------------------------------------------------------
// Local attention: one warp per (row, head); block = 8 consecutive s x one
// head (locality remap). qkv fp32 in; att fp16 (perm16) out.
// ---------------------------------------------------------------------------
__global__ __launch_bounds__(256) void local_attn_kernel(
    const float* __restrict__ qkv, const float* __restrict__ bias,
    __half* __restrict__ out)
{
    const int w    = threadIdx.x >> 5;
    const int lane = threadIdx.x & 31;
    const int sblk = blockIdx.x & (SEQ / 8 - 1);
    const int h    = (blockIdx.x >> 5) & (HEADS - 1);
    const int bhw  = blockIdx.x >> 8;
    const int s = sblk * 8 + w;
    const int r = bhw * SEQ + s;

    const float* qrow = qkv + (size_t)r * QKV_N + h * DK;
    const float q0 = qrow[lane];
    const float q1 = qrow[lane + 32];

    float logit[KSIZE];
    #pragma unroll
    for (int ww = 0; ww < KSIZE; ww++) {
        const int sn = s + ww - NEIGH;
        float dot = 0.0f;
        if (sn >= 0 && sn < SEQ) {
            const float* krow = qkv + (size_t)(r + ww - NEIGH) * QKV_N
                                + HEADS * DK + h * DK;
            float t = q0 * krow[lane] + q1 * krow[lane + 32];
            #pragma unroll
            for (int off = 16; off > 0; off >>= 1)
                t += __shfl_xor_sync(0xFFFFFFFFu, t, off);
            dot = t;
        }
        logit[ww] = dot * 0.125f + bias[((size_t)h * SEQ + s) * KSIZE + ww];
    }

    float m = logit[0];
    #pragma unroll
    for (int ww = 1; ww < KSIZE; ww++) m = fmaxf(m, logit[ww]);
    float p[KSIZE];
    float denom = 0.0f;
    #pragma unroll
    for (int ww = 0; ww < KSIZE; ww++) {
        p[ww] = __expf(logit[ww] - m);
        denom += p[ww];
    }
    const float inv = 1.0f / denom;

    float o0 = 0.0f, o1 = 0.0f;
    #pragma unroll
    for (int ww = 0; ww < KSIZE; ww++) {
        const int sn = s + ww - NEIGH;
        if (sn >= 0 && sn < SEQ) {
            const float* vrow = qkv + (size_t)(r + ww - NEIGH) * QKV_N
                                + 2 * HEADS * DK + h * DK;
            o0 += p[ww] * vrow[lane];
            o1 += p[ww] * vrow[lane + 32];
        }
    }
    __half* orow = out + (size_t)r * DMODEL;
    orow[perm16(h * DK + lane)]      = __float2half_rn(o0 * inv);
    orow[perm16(h * DK + lane + 32)] = __float2half_rn(o1 * inv);
}

// ---------------------------------------------------------------------------
// Launch: 4 row-chunks pipelined across 2 streams (halo never crosses a
// chunk boundary: chunks are whole (b,hw) sequences).
// ---------------------------------------------------------------------------
extern "C" void kernel_launch(void* const* d_in, const int* in_sizes, int n_in,
                              void* d_out, int out_size)
{
    const float* x    = (const float*)d_in[0];  // [2,64,256,512]
    const float* bias = (const float*)d_in[1];  // [8,256,7]
    const float* Wqkv = (const float*)d_in[2];  // [512,1536]
    const float* Wout = (const float*)d_in[3];  // [512,512]
    float* out        = (float*)d_out;          // [32768,512]

    __half *xt, *att, *wqkvT, *woutT;
    float *qkv;
    cudaGetSymbolAddress((void**)&xt,    g_xt);
    cudaGetSymbolAddress((void**)&qkv,   g_qkv);
    cudaGetSymbolAddress((void**)&att,   g_att);
    cudaGetSymbolAddress((void**)&wqkvT, g_wqkvT);
    cudaGetSymbolAddress((void**)&woutT, g_woutT);

    const int dyn_smem = 2 * (BM + BN) * XSH * (int)sizeof(__half);  // 81920

    static cudaStream_t st[2] = {nullptr, nullptr};
    static cudaEvent_t evFork = nullptr;
    static cudaEvent_t evJoin[2] = {nullptr, nullptr};
    static bool init_done = false;
    if (!init_done) {
        cudaFuncSetAttribute(gemm_mma_f16<DMODEL>,
                             cudaFuncAttributeMaxDynamicSharedMemorySize, dyn_smem);
        cudaStreamCreateWithFlags(&st[0], cudaStreamNonBlocking);
        cudaStreamCreateWithFlags(&st[1], cudaStreamNonBlocking);
        cudaEventCreateWithFlags(&evFork,    cudaEventDisableTiming);
        cudaEventCreateWithFlags(&evJoin[0], cudaEventDisableTiming);
        cudaEventCreateWithFlags(&evJoin[1], cudaEventDisableTiming);
        init_done = true;
    }

    // Shared prep on the (captured) default stream
    {
        dim3 blk(32, 8);
        transpose_kernel<<<dim3(QKV_N / 32, DMODEL / 32), blk>>>(Wqkv, wqkvT,
                                                                 DMODEL, QKV_N);
        transpose_kernel<<<dim3(DMODEL / 32, DMODEL / 32), blk>>>(Wout, woutT,
                                                                  DMODEL, DMODEL);
    }
    cudaEventRecord(evFork, 0);
    cudaStreamWaitEvent(st[0], evFork, 0);
    cudaStreamWaitEvent(st[1], evFork, 0);

    for (int c = 0; c < NCHUNK; c++) {
        cudaStream_t s = st[c & 1];
        const size_t ro = (size_t)c * CHROWS;
        const float* xc = x   + ro * DMODEL;
        __half* xtc     = xt  + ro * DMODEL;
        float* qkvc     = qkv + ro * QKV_N;
        __half* attc    = att + ro * DMODEL;
        float* outc     = out + ro * DMODEL;

        const int n16 = CHROWS * DMODEL / 16;
        conv_perm_kernel<<<(n16 + 255) / 256, 256, 0, s>>>(
            (const float4*)xc, xtc, n16);

        gemm_mma_f16<DMODEL><<<dim3(QKV_N / BN, CHROWS / BM),
                               GEMM_THREADS, dyn_smem, s>>>(
            xtc, wqkvT, qkvc, CHROWS, QKV_N);

        local_attn_kernel<<<CHROWS, 256, 0, s>>>(qkvc, bias, attc);

        gemm_mma_f16<DMODEL><<<dim3(DMODEL / BN, CHROWS / BM),
                               GEMM_THREADS, dyn_smem, s>>>(
            attc, woutT, outc, CHROWS, DMODEL);
    }

    cudaEventRecord(evJoin[0], st[0]);
    cudaEventRecord(evJoin[1], st[1]);
    cudaStreamWaitEvent(0, evJoin[0], 0);
    cudaStreamWaitEvent(0, evJoin[1], 0);
}